// round 15
// baseline (speedup 1.0000x reference)
#include <cuda_runtime.h>
#include <cuda_bf16.h>
#include <cstdint>

// Shapes: query [64,512,512] (n,d,c); key/value [64,512,1024] (n,d,t); out [64,512,512]
#define NB 64
#define DD 512
#define CC 512
#define TT 1024
#define WDIM 128
#define SCALE_F 0.04419417382415922f   // 512^-0.5

// tcgen05 is arch-specific: only under sm_10xa passes.
#if defined(__CUDA_ARCH_FEAT_SM103_ALL) || defined(__CUDA_ARCH_FEAT_SM101_ALL) || \
    defined(__CUDA_ARCH_FEAT_SM100_ALL) || \
    (defined(__CUDA_ARCH_SPECIFIC__) && (__CUDA_ARCH_SPECIFIC__ >= 1000))
#define USE_TCGEN05 1
#else
#define USE_TCGEN05 0
#endif

// ---------------- scratch (device globals; no allocation) ----------------
__device__ float g_logits[(size_t)NB * CC * TT];                       // 134 MB
__device__ __align__(16) __nv_bfloat16 g_Qth[(size_t)NB * CC * DD];    // Qt[c][d] hi
__device__ __align__(16) __nv_bfloat16 g_Qtl[(size_t)NB * CC * DD];
__device__ __align__(16) __nv_bfloat16 g_Kth[(size_t)NB * TT * DD];    // Kt[t][d]
__device__ __align__(16) __nv_bfloat16 g_Ktl[(size_t)NB * TT * DD];
__device__ __align__(16) __nv_bfloat16 g_Wh [(size_t)NB * CC * TT];    // W[c][t]
__device__ __align__(16) __nv_bfloat16 g_Wl [(size_t)NB * CC * TT];

// ---------------- common helpers ----------------
__device__ __forceinline__ uint32_t smem_to_u32(const void* p) {
    uint32_t a;
    asm("{ .reg .u64 t; cvta.to.shared.u64 t, %1; cvt.u32.u64 %0, t; }" : "=r"(a) : "l"(p));
    return a;
}
__device__ __forceinline__ void split2(float x, __nv_bfloat16& h, __nv_bfloat16& l) {
    h = __float2bfloat16(x);
    l = __float2bfloat16(x - __bfloat162float(h));   // exact residual
}
// pack 4 bf16 into one 8-byte value
__device__ __forceinline__ unsigned long long pack4(__nv_bfloat16 a, __nv_bfloat16 b,
                                                    __nv_bfloat16 c, __nv_bfloat16 d) {
    __nv_bfloat162 p0(a, b), p1(c, d);
    uint32_t u0 = *reinterpret_cast<uint32_t*>(&p0);
    uint32_t u1 = *reinterpret_cast<uint32_t*>(&p1);
    unsigned long long r;
    asm("mov.b64 %0, {%1, %2};" : "=l"(r) : "r"(u0), "r"(u1));
    return r;
}
#define FMA2(d, a, b) \
    asm("fma.rn.f32x2 %0, %1, %2, %0;" : "+l"(d) : "l"(a), "l"(b))
__device__ __forceinline__ unsigned long long pack_dup(float x) {
    unsigned long long r;
    unsigned int u = __float_as_uint(x);
    asm("mov.b64 %0, {%1, %2};" : "=l"(r) : "r"(u), "r"(u));
    return r;
}
__device__ __forceinline__ float2 bf2_to_f2(uint32_t u) {
    __nv_bfloat162 b = *reinterpret_cast<__nv_bfloat162*>(&u);
    return __bfloat1622float2(b);
}

#if USE_TCGEN05
// ---------------- PTX helpers (sm_103a-only pass) ----------------
__device__ __forceinline__ uint32_t elect_one_pred() {
    uint32_t pred;
    asm volatile("{\n\t.reg .pred p;\n\telect.sync _|p, 0xFFFFFFFF;\n\tselp.b32 %0, 1, 0, p;\n\t}" : "=r"(pred));
    return pred;
}
#define MBARRIER_INIT(a, c) \
    asm volatile("mbarrier.init.shared.b64 [%0], %1;" :: "r"((uint32_t)(a)), "r"((uint32_t)(c)) : "memory")
#define MBARRIER_INVAL(a) \
    asm volatile("mbarrier.inval.shared.b64 [%0];" :: "r"((uint32_t)(a)) : "memory")
#define MBARRIER_ARRIVE(a) \
    asm volatile("mbarrier.arrive.shared.b64 _, [%0];" :: "r"((uint32_t)(a)) : "memory")
#define MBARRIER_WAIT_PARITY(mbar_smem_addr, phase_parity) do { \
    uint32_t _mbar = (uint32_t)(mbar_smem_addr); \
    uint32_t _parity = (uint32_t)(phase_parity); \
    uint32_t _done; \
    asm volatile("{\n\t.reg .pred p;\n\t" \
        "mbarrier.try_wait.parity.acquire.cta.shared::cta.b64 p, [%1], %2;\n\t" \
        "selp.b32 %0, 1, 0, p;\n\t}" \
        : "=r"(_done) : "r"(_mbar), "r"(_parity) : "memory"); \
    if (!_done) { \
        asm volatile("{\n\t.reg .pred P1;\n\t" \
            "WAIT_LOOP_%=:\n\t" \
            "mbarrier.try_wait.parity.acquire.cta.shared::cta.b64 P1, [%0], %1, 0x989680;\n\t" \
            "@P1 bra.uni WAIT_DONE_%=;\n\t" \
            "bra.uni WAIT_LOOP_%=;\n\t" \
            "WAIT_DONE_%=:\n\t}" \
            :: "r"(_mbar), "r"(_parity) : "memory"); \
    } \
} while(0)
#define TCGEN05_ALLOC(sa, n) \
    asm volatile("tcgen05.alloc.cta_group::1.sync.aligned.shared::cta.b32 [%0], %1;" \
                 :: "r"((uint32_t)(sa)), "r"((uint32_t)(n)) : "memory")
#define TCGEN05_DEALLOC(t, n) \
    asm volatile("tcgen05.dealloc.cta_group::1.sync.aligned.b32 %0, %1;" :: "r"(t), "r"((uint32_t)(n)))
#define TCGEN05_RELINQUISH() \
    asm volatile("tcgen05.relinquish_alloc_permit.cta_group::1.sync.aligned;")
#define TCGEN05_COMMIT(a) \
    asm volatile("tcgen05.commit.cta_group::1.mbarrier::arrive::one.shared::cluster.b64 [%0];" \
                 :: "r"((uint32_t)(a)) : "memory")
#define TCGEN05_FENCE_AFTER()  asm volatile("tcgen05.fence::after_thread_sync;" ::: "memory")
#define TCGEN05_FENCE_BEFORE() asm volatile("tcgen05.fence::before_thread_sync;" ::: "memory")
#define TCGEN05_WAIT_LD()      asm volatile("tcgen05.wait::ld.sync.aligned;" ::: "memory")
#define FENCE_PROXY_ASYNC()    asm volatile("fence.proxy.async.shared::cta;" ::: "memory")
#define CP_ASYNC_16(dst, src) \
    asm volatile("cp.async.cg.shared.global [%0], [%1], 16;" :: "r"((uint32_t)(dst)), "l"(src) : "memory")
// completion-gated arrival: fires one arrival on [bar] when all prior cp.async
// of this thread have completed. .noinc => expected count fixed at init.
#define CP_ASYNC_MBAR_ARRIVE(bar) \
    asm volatile("cp.async.mbarrier.arrive.noinc.shared.b64 [%0];" :: "r"((uint32_t)(bar)) : "memory")

#define TCGEN05_LD_32X32B_X32(r, ta) \
    asm volatile( \
        "tcgen05.ld.sync.aligned.32x32b.x32.b32 " \
        "{%0, %1, %2, %3, %4, %5, %6, %7, " \
        " %8, %9, %10, %11, %12, %13, %14, %15, " \
        " %16, %17, %18, %19, %20, %21, %22, %23, " \
        " %24, %25, %26, %27, %28, %29, %30, %31}, [%32];" \
        : "=r"((r)[0]),  "=r"((r)[1]),  "=r"((r)[2]),  "=r"((r)[3]), \
          "=r"((r)[4]),  "=r"((r)[5]),  "=r"((r)[6]),  "=r"((r)[7]), \
          "=r"((r)[8]),  "=r"((r)[9]),  "=r"((r)[10]), "=r"((r)[11]), \
          "=r"((r)[12]), "=r"((r)[13]), "=r"((r)[14]), "=r"((r)[15]), \
          "=r"((r)[16]), "=r"((r)[17]), "=r"((r)[18]), "=r"((r)[19]), \
          "=r"((r)[20]), "=r"((r)[21]), "=r"((r)[22]), "=r"((r)[23]), \
          "=r"((r)[24]), "=r"((r)[25]), "=r"((r)[26]), "=r"((r)[27]), \
          "=r"((r)[28]), "=r"((r)[29]), "=r"((r)[30]), "=r"((r)[31]) \
        : "r"(ta))

static constexpr uint64_t DESC_BASE_SW128 =
    (uint64_t(2) << 61) | (uint64_t(1) << 46) | (uint64_t(64) << 32) | (uint64_t(1) << 16);
#define MAKE_DESC(sa) (DESC_BASE_SW128 | ((uint64_t)((sa) >> 4) & 0x3FFF))
#define SMEM_SWIZZLE_128B(b)   ((b) ^ (((b) >> 3) & 0x70))

// idesc kind::f16, bf16 x bf16 -> f32, M=128, N=128
static constexpr uint32_t GEMM_IDESC =
    (1u << 4) | (1u << 7) | (1u << 10) | ((128u / 8) << 17) | ((128u / 16) << 24);

__device__ __forceinline__ void mma_f16_ss(uint32_t d, uint64_t a, uint64_t b,
                                           uint32_t idesc, uint32_t en) {
    asm volatile(
        "{\n\t.reg .pred p;\n\tsetp.ne.u32 p, %4, 0;\n\t"
        "tcgen05.mma.cta_group::1.kind::f16 [%0], %1, %2, %3, {%5, %5, %5, %5}, p;\n\t}"
        :: "r"(d), "l"(a), "l"(b), "r"(idesc), "r"(en), "r"(0u) : "memory");
}
#endif // USE_TCGEN05

// ---------------- pre-pass: transpose + split (Q, K only) ----------------
// src [n][R][L] fp32 (L contiguous) -> dh/dl [n][L][R] bf16 (bf162 stores)
__global__ __launch_bounds__(256) void transpose_split_kernel(
    const float* __restrict__ src, __nv_bfloat16* __restrict__ dh,
    __nv_bfloat16* __restrict__ dl, int R, int L) {
    __shared__ float tile[32][33];
    const int n = blockIdx.z;
    const float* s = src + (size_t)n * R * L;
    __nv_bfloat16* ph = dh + (size_t)n * R * L;
    __nv_bfloat16* pl = dl + (size_t)n * R * L;
    const int tx = threadIdx.x, ty = threadIdx.y;
    const int x  = blockIdx.x * 32 + tx;    // L index
    const int y0 = blockIdx.y * 32;         // R base
    #pragma unroll
    for (int j = 0; j < 4; j++)
        tile[ty + j * 8][tx] = s[(size_t)(y0 + ty + j * 8) * L + x];
    __syncthreads();
    const int yb  = blockIdx.x * 32;        // L base
    const int tid = ty * 32 + tx;
    #pragma unroll
    for (int it = 0; it < 2; it++) {
        const int wi = tid + it * 256;      // 0..511
        const int yo = wi >> 4;             // L col 0..31
        const int p  = wi & 15;             // R pair 0..15
        float v0 = tile[2 * p + 0][yo];
        float v1 = tile[2 * p + 1][yo];
        __nv_bfloat16 h0, l0, h1, l1;
        split2(v0, h0, l0); split2(v1, h1, l1);
        const size_t o = ((size_t)(yb + yo) * R + y0 + 2 * p) >> 1;
        ((__nv_bfloat162*)ph)[o] = __nv_bfloat162(h0, h1);
        ((__nv_bfloat162*)pl)[o] = __nv_bfloat162(l0, l1);
    }
}

// ---------------- softmax: logits fp32 -> W bf16 hi/lo ----------------
__global__ __launch_bounds__(256) void softmax_kernel(const float* __restrict__ ratios) {
    const int warp = threadIdx.x >> 5;
    const int lane = threadIdx.x & 31;
    const int row  = blockIdx.x * 8 + warp;   // n*CC + c
    const int n    = row >> 9;
    const float r = ratios[n];
    const int vw  = min(WDIM, (int)floorf((float)WDIM * r + 0.5f));

    const float* p = g_logits + (size_t)row * TT;
    float v[32];
    float mx = -INFINITY;
    #pragma unroll
    for (int i = 0; i < 32; i++) {
        const int t = lane + i * 32;
        float x = p[t] * SCALE_F;
        if ((t & (WDIM - 1)) >= vw) x = -INFINITY;
        v[i] = x; mx = fmaxf(mx, x);
    }
    #pragma unroll
    for (int off = 16; off > 0; off >>= 1)
        mx = fmaxf(mx, __shfl_xor_sync(0xffffffffu, mx, off));
    float s = 0.0f;
    #pragma unroll
    for (int i = 0; i < 32; i++) { const float e = expf(v[i] - mx); v[i] = e; s += e; }
    #pragma unroll
    for (int off = 16; off > 0; off >>= 1)
        s += __shfl_xor_sync(0xffffffffu, s, off);
    const float inv = 1.0f / s;
    __nv_bfloat16* wh = g_Wh + (size_t)row * TT;
    __nv_bfloat16* wl = g_Wl + (size_t)row * TT;
    #pragma unroll
    for (int i = 0; i < 32; i++) {
        __nv_bfloat16 h, l; split2(v[i] * inv, h, l);
        wh[lane + i * 32] = h; wl[lane + i * 32] = l;
    }
}

// ---------------- GEMM: D[m][nn] = sum_k A[m][k]*B[nn][k] ----------------
// Warp-specialized tcgen05, 384 threads: warp 0 = MMA issuer (queue-paced),
// warps 4-7 = A producer, warps 8-11 = B producer (cp.async), 3-stage ring.
// CONV_A: A producer reads fp32 source and splits to bf16 hi/lo in-flight
// (eliminates the separate split pre-pass); else A via cp.async from bf16.
// full[s] count=256 (128 A arrivals + 128 B cp.async-completion arrivals).
#define SM_TMEM  0
#define SM_FULL  8     // 3 x 8B
#define SM_EMPTY 32    // 3 x 8B
#define SM_DONE  56    // 8B, single-use
#define SM_DATA  1024
#define TILE_B   16384
#define STAGES   3
#define GEMM_SMEM (1024 + STAGES * 4 * TILE_B)   // 197632 B

template <bool CONV_A>
__global__ __launch_bounds__(384, 1)
void gemm_split_kernel(const float* __restrict__ Afp,
                       const __nv_bfloat16* __restrict__ Ah, const __nv_bfloat16* __restrict__ Al,
                       const __nv_bfloat16* __restrict__ Bh, const __nv_bfloat16* __restrict__ Bl,
                       float* __restrict__ C, int Kdim, int ldc,
                       size_t sA, size_t sB, size_t sC) {
    extern __shared__ char smem[];
    const int tid = threadIdx.x, wid = tid >> 5, lane = tid & 31;
    const int nz = blockIdx.z, m0 = blockIdx.y * 128, n0 = blockIdx.x * 128;

#if USE_TCGEN05
    const uint32_t sb = smem_to_u32(smem);

    if (wid == 0) { TCGEN05_ALLOC(sb + SM_TMEM, 128); TCGEN05_RELINQUISH(); }
    if (tid == 0) {
        #pragma unroll
        for (int s = 0; s < STAGES; s++) {
            MBARRIER_INIT(sb + SM_FULL  + 8 * s, 256);  // 128 A + 128 B arrivals
            MBARRIER_INIT(sb + SM_EMPTY + 8 * s, 1);    // tcgen05 commit
        }
        MBARRIER_INIT(sb + SM_DONE, 1);                 // final completion
    }
    __syncthreads();
    uint32_t tmem;
    asm volatile("ld.shared.b32 %0, [%1];" : "=r"(tmem) : "r"(sb + SM_TMEM));

    const int nch = Kdim >> 6;

    if (wid >= 4 && wid < 8) {
        // ---- A producer (128 threads) ----
        const int f = tid - 128;              // 0..127
        for (int ch = 0; ch < nch; ch++) {
            const int s = ch % STAGES;
            if (ch >= STAGES)
                MBARRIER_WAIT_PARITY(sb + SM_EMPTY + 8 * s, ((ch - STAGES) / STAGES) & 1);
            const int k0 = ch << 6;
            if (CONV_A) {
                // read fp32 A, split to bf16 hi/lo, store swizzled
                const float* gs = Afp + nz * sA + (size_t)m0 * Kdim + k0;
                char* tbh = smem + SM_DATA + (size_t)(s * 4 + 0) * TILE_B;
                char* tbl = smem + SM_DATA + (size_t)(s * 4 + 1) * TILE_B;
                #pragma unroll
                for (int i = 0; i < 16; i++) {
                    const int idx = f + 128 * i;
                    const int r = idx >> 4, c4 = idx & 15;
                    float4 u = *(const float4*)(gs + (size_t)r * Kdim + c4 * 4);
                    __nv_bfloat16 h0, l0, h1, l1, h2, l2, h3, l3;
                    split2(u.x, h0, l0); split2(u.y, h1, l1);
                    split2(u.z, h2, l2); split2(u.w, h3, l3);
                    const uint32_t off = SMEM_SWIZZLE_128B((uint32_t)(r * 128 + c4 * 8));
                    *(unsigned long long*)(tbh + off) = pack4(h0, h1, h2, h3);
                    *(unsigned long long*)(tbl + off) = pack4(l0, l1, l2, l3);
                }
                MBARRIER_ARRIVE(sb + SM_FULL + 8 * s);   // release-arrive after STS
            } else {
                #pragma unroll
                for (int tg = 0; tg < 2; tg++) {
                    const uint32_t tb = sb + SM_DATA + (uint32_t)(s * 4 + tg) * TILE_B;
                    const __nv_bfloat16* gs =
                        (tg ? Al : Ah) + nz * sA + (size_t)m0 * Kdim + k0;
                    #pragma unroll
                    for (int i = 0; i < 8; i++) {
                        const int idx = f + 128 * i;
                        const int r = idx >> 3, c = idx & 7;
                        const uint32_t dst = tb + SMEM_SWIZZLE_128B((uint32_t)(r * 128 + c * 16));
                        CP_ASYNC_16(dst, (const void*)(gs + (size_t)r * Kdim + c * 8));
                    }
                }
                CP_ASYNC_MBAR_ARRIVE(sb + SM_FULL + 8 * s);
            }
        }
    } else if (wid >= 8) {
        // ---- B producer (128 threads, cp.async) ----
        const int f = tid - 256;
        for (int ch = 0; ch < nch; ch++) {
            const int s = ch % STAGES;
            if (ch >= STAGES)
                MBARRIER_WAIT_PARITY(sb + SM_EMPTY + 8 * s, ((ch - STAGES) / STAGES) & 1);
            const int k0 = ch << 6;
            #pragma unroll
            for (int tg = 0; tg < 2; tg++) {
                const uint32_t tb = sb + SM_DATA + (uint32_t)(s * 4 + 2 + tg) * TILE_B;
                const __nv_bfloat16* gs =
                    (tg ? Bl : Bh) + nz * sB + (size_t)n0 * Kdim + k0;
                #pragma unroll
                for (int i = 0; i < 8; i++) {
                    const int idx = f + 128 * i;
                    const int r = idx >> 3, c = idx & 7;
                    const uint32_t dst = tb + SMEM_SWIZZLE_128B((uint32_t)(r * 128 + c * 16));
                    CP_ASYNC_16(dst, (const void*)(gs + (size_t)r * Kdim + c * 8));
                }
            }
            CP_ASYNC_MBAR_ARRIVE(sb + SM_FULL + 8 * s);
        }
    } else if (wid == 0) {
        // ---- consumer: MMA issue, paced by tensor queue ----
        for (int ch = 0; ch < nch; ch++) {
            const int s = ch % STAGES;
            MBARRIER_WAIT_PARITY(sb + SM_FULL + 8 * s, (ch / STAGES) & 1);
            FENCE_PROXY_ASYNC();
            if (elect_one_pred()) {
                const uint64_t dAh = MAKE_DESC(sb + SM_DATA + (s * 4 + 0) * TILE_B);
                const uint64_t dAl = MAKE_DESC(sb + SM_DATA + (s * 4 + 1) * TILE_B);
                const uint64_t dBh = MAKE_DESC(sb + SM_DATA + (s * 4 + 2) * TILE_B);
                const uint64_t dBl = MAKE_DESC(sb + SM_DATA + (s * 4 + 3) * TILE_B);
                #pragma unroll
                for (int p = 0; p < 3; p++) {
                    const uint64_t da = (p == 2) ? dAl : dAh;
                    const uint64_t db = (p == 1) ? dBl : dBh;
                    #pragma unroll
                    for (int ks = 0; ks < 4; ks++) {
                        const uint32_t en = !(ch == 0 && p == 0 && ks == 0);
                        mma_f16_ss(tmem, da + ks * 2, db + ks * 2, GEMM_IDESC, en);
                    }
                }
                TCGEN05_COMMIT(sb + SM_EMPTY + 8 * s);
            }
        }
        // single-use completion signal: fires when ALL prior MMAs complete
        if (elect_one_pred()) TCGEN05_COMMIT(sb + SM_DONE);
    }
    // ---- all warps: unambiguous final wait (done used exactly once) ----
    MBARRIER_WAIT_PARITY(sb + SM_DONE, 0);
    TCGEN05_FENCE_AFTER();

    if (wid < 4) {
        float* Crow = C + nz * sC + (size_t)(m0 + wid * 32 + lane) * ldc + n0;
        #pragma unroll
        for (int nb = 0; nb < 4; nb++) {
            uint32_t r[32];
            TCGEN05_LD_32X32B_X32(r, tmem + nb * 32);
            TCGEN05_WAIT_LD();
            #pragma unroll
            for (int j = 0; j < 8; j++) {
                float4 v;
                v.x = __uint_as_float(r[j * 4 + 0]);
                v.y = __uint_as_float(r[j * 4 + 1]);
                v.z = __uint_as_float(r[j * 4 + 2]);
                v.w = __uint_as_float(r[j * 4 + 3]);
                *(float4*)(Crow + nb * 32 + j * 4) = v;
            }
        }
        TCGEN05_FENCE_BEFORE();
    }
    __syncthreads();
    if (tid == 0) {
        #pragma unroll
        for (int s = 0; s < STAGES; s++) {
            MBARRIER_INVAL(sb + SM_FULL + 8 * s);
            MBARRIER_INVAL(sb + SM_EMPTY + 8 * s);
        }
        MBARRIER_INVAL(sb + SM_DONE);
    }
    __syncthreads();
    if (wid == 0) TCGEN05_DEALLOC(tmem, 128);

#else
    // ---- SIMT fallback: fp32 128x128 tile, 8x8/thread (threads 0-255) ----
    float* As = (float*)smem;                       // [16][136]
    float* Bs = (float*)(smem + 16 * 136 * 4);      // [16][136]
    const int tx = tid & 15;
    const int ty = (tid & 255) >> 4;
    const int lr = (tid & 255) >> 1;
    const int lk = (tid & 1) * 8;
    const bool active = tid < 256;

    unsigned long long acc[8][4];
    #pragma unroll
    for (int i = 0; i < 8; i++)
        #pragma unroll
        for (int j = 0; j < 4; j++) acc[i][j] = 0ull;

    for (int k0 = 0; k0 < Kdim; k0 += 16) {
        if (active) {
            if (CONV_A) {
                const float* pA = Afp + nz * sA + (size_t)m0 * Kdim;
                const float4 u0 = *(const float4*)(pA + (size_t)lr * Kdim + k0 + lk);
                const float4 u1 = *(const float4*)(pA + (size_t)lr * Kdim + k0 + lk + 4);
                const float fv[8] = {u0.x, u0.y, u0.z, u0.w, u1.x, u1.y, u1.z, u1.w};
                #pragma unroll
                for (int j = 0; j < 8; j++)
                    As[(lk + j) * 136 + lr] = fv[j];
            } else {
                const __nv_bfloat16* pAh = Ah + nz * sA + (size_t)m0 * Kdim;
                const __nv_bfloat16* pAl = Al + nz * sA + (size_t)m0 * Kdim;
                uint4 uh = *(const uint4*)(pAh + (size_t)lr * Kdim + k0 + lk);
                uint4 ul = *(const uint4*)(pAl + (size_t)lr * Kdim + k0 + lk);
                const uint32_t hh[4] = {uh.x, uh.y, uh.z, uh.w};
                const uint32_t ll[4] = {ul.x, ul.y, ul.z, ul.w};
                #pragma unroll
                for (int j = 0; j < 4; j++) {
                    float2 h = bf2_to_f2(hh[j]), l = bf2_to_f2(ll[j]);
                    As[(lk + j * 2 + 0) * 136 + lr] = h.x + l.x;
                    As[(lk + j * 2 + 1) * 136 + lr] = h.y + l.y;
                }
            }
            {
                const __nv_bfloat16* pBh = Bh + nz * sB + (size_t)n0 * Kdim;
                const __nv_bfloat16* pBl = Bl + nz * sB + (size_t)n0 * Kdim;
                uint4 uh = *(const uint4*)(pBh + (size_t)lr * Kdim + k0 + lk);
                uint4 ul = *(const uint4*)(pBl + (size_t)lr * Kdim + k0 + lk);
                const uint32_t hh[4] = {uh.x, uh.y, uh.z, uh.w};
                const uint32_t ll[4] = {ul.x, ul.y, ul.z, ul.w};
                #pragma unroll
                for (int j = 0; j < 4; j++) {
                    float2 h = bf2_to_f2(hh[j]), l = bf2_to_f2(ll[j]);
                    Bs[(lk + j * 2 + 0) * 136 + lr] = h.x + l.x;
                    Bs[(lk + j * 2 + 1) * 136 + lr] = h.y + l.y;
                }
            }
        }
        __syncthreads();
        if (active) {
            #pragma unroll
            for (int kk = 0; kk < 16; kk++) {
                float4 a0 = *(const float4*)&As[kk * 136 + ty * 8 + 0];
                float4 a1 = *(const float4*)&As[kk * 136 + ty * 8 + 4];
                unsigned long long b0 = *(const unsigned long long*)&Bs[kk * 136 + tx * 8 + 0];
                unsigned long long b1 = *(const unsigned long long*)&Bs[kk * 136 + tx * 8 + 2];
                unsigned long long b2 = *(const unsigned long long*)&Bs[kk * 136 + tx * 8 + 4];
                unsigned long long b3 = *(const unsigned long long*)&Bs[kk * 136 + tx * 8 + 6];
                float am[8] = {a0.x, a0.y, a0.z, a0.w, a1.x, a1.y, a1.z, a1.w};
                #pragma unroll
                for (int m = 0; m < 8; m++) {
                    unsigned long long A2 = pack_dup(am[m]);
                    FMA2(acc[m][0], A2, b0);
                    FMA2(acc[m][1], A2, b1);
                    FMA2(acc[m][2], A2, b2);
                    FMA2(acc[m][3], A2, b3);
                }
            }
        }
        __syncthreads();
    }

    if (active) {
        #pragma unroll
        for (int m = 0; m < 8; m++) {
            float* Crow = C + nz * sC + (size_t)(m0 + ty * 8 + m) * ldc + n0 + tx * 8;
            #pragma unroll
            for (int p = 0; p < 4; p++)
                *(unsigned long long*)(Crow + p * 2) = acc[m][p];
        }
    }
#endif
}

// ---------------- launch ----------------
extern "C" void kernel_launch(void* const* d_in, const int* in_sizes, int n_in,
                              void* d_out, int out_size) {
    const float* q      = (const float*)d_in[0];
    const float* k      = (const float*)d_in[1];
    const float* v      = (const float*)d_in[2];
    const float* ratios = (const float*)d_in[3];
    float* out = (float*)d_out;
    (void)in_sizes; (void)n_in; (void)out_size;

    float* lg; __nv_bfloat16 *qh, *ql, *kh, *kl, *wh, *wl;
    cudaGetSymbolAddress((void**)&lg, g_logits);
    cudaGetSymbolAddress((void**)&qh, g_Qth); cudaGetSymbolAddress((void**)&ql, g_Qtl);
    cudaGetSymbolAddress((void**)&kh, g_Kth); cudaGetSymbolAddress((void**)&kl, g_Ktl);
    cudaGetSymbolAddress((void**)&wh, g_Wh);  cudaGetSymbolAddress((void**)&wl, g_Wl);

    cudaFuncSetAttribute(gemm_split_kernel<false>,
                         cudaFuncAttributeMaxDynamicSharedMemorySize, GEMM_SMEM);
    cudaFuncSetAttribute(gemm_split_kernel<true>,
                         cudaFuncAttributeMaxDynamicSharedMemorySize, GEMM_SMEM);

    // pre-pass: Qt[c][d], Kt[t][d] (V split is fused into GEMM2's producer)
    transpose_split_kernel<<<dim3(CC / 32, DD / 32, NB), dim3(32, 8)>>>(q, qh, ql, DD, CC);
    transpose_split_kernel<<<dim3(TT / 32, DD / 32, NB), dim3(32, 8)>>>(k, kh, kl, DD, TT);

    // GEMM1: logits[c][t] = Qt[c][:] . Kt[t][:]   (K=512), A via cp.async
    gemm_split_kernel<false><<<dim3(TT / 128, CC / 128, NB), 384, GEMM_SMEM>>>(
        nullptr, qh, ql, kh, kl, lg, DD, TT,
        (size_t)CC * DD, (size_t)TT * DD, (size_t)CC * TT);

    softmax_kernel<<<(NB * CC) / 8, 256>>>(ratios);

    // GEMM2: out[dd][c] = V[dd][:] . W[c][:]      (K=1024), A = fp32 V split in-flight
    gemm_split_kernel<true><<<dim3(CC / 128, DD / 128, NB), 384, GEMM_SMEM>>>(
        v, nullptr, nullptr, wh, wl, out, TT, CC,
        (size_t)DD * TT, (size_t)CC * TT, (size_t)DD * CC);
}

// round 16
// speedup vs baseline: 1.1684x; 1.1684x over previous
#include <cuda_runtime.h>
#include <cuda_bf16.h>
#include <cstdint>

// Shapes: query [64,512,512] (n,d,c); key/value [64,512,1024] (n,d,t); out [64,512,512]
#define NB 64
#define DD 512
#define CC 512
#define TT 1024
#define WDIM 128
#define SCALE_F 0.04419417382415922f   // 512^-0.5

// tcgen05 is arch-specific: only under sm_10xa passes.
#if defined(__CUDA_ARCH_FEAT_SM103_ALL) || defined(__CUDA_ARCH_FEAT_SM101_ALL) || \
    defined(__CUDA_ARCH_FEAT_SM100_ALL) || \
    (defined(__CUDA_ARCH_SPECIFIC__) && (__CUDA_ARCH_SPECIFIC__ >= 1000))
#define USE_TCGEN05 1
#else
#define USE_TCGEN05 0
#endif

// ---------------- scratch (device globals; no allocation) ----------------
__device__ float g_logits[(size_t)NB * CC * TT];                       // 134 MB
__device__ __align__(16) __nv_bfloat16 g_Qth[(size_t)NB * CC * DD];    // Qt[c][d] hi
__device__ __align__(16) __nv_bfloat16 g_Qtl[(size_t)NB * CC * DD];
__device__ __align__(16) __nv_bfloat16 g_Kth[(size_t)NB * TT * DD];    // Kt[t][d]
__device__ __align__(16) __nv_bfloat16 g_Ktl[(size_t)NB * TT * DD];
__device__ __align__(16) __nv_bfloat16 g_Wh [(size_t)NB * CC * TT];    // W[c][t]
__device__ __align__(16) __nv_bfloat16 g_Wl [(size_t)NB * CC * TT];

// ---------------- common helpers ----------------
__device__ __forceinline__ uint32_t smem_to_u32(const void* p) {
    uint32_t a;
    asm("{ .reg .u64 t; cvta.to.shared.u64 t, %1; cvt.u32.u64 %0, t; }" : "=r"(a) : "l"(p));
    return a;
}
__device__ __forceinline__ void split2(float x, __nv_bfloat16& h, __nv_bfloat16& l) {
    h = __float2bfloat16(x);
    l = __float2bfloat16(x - __bfloat162float(h));   // exact residual
}
// pack 4 bf16 into one 8-byte value
__device__ __forceinline__ unsigned long long pack4(__nv_bfloat16 a, __nv_bfloat16 b,
                                                    __nv_bfloat16 c, __nv_bfloat16 d) {
    __nv_bfloat162 p0(a, b), p1(c, d);
    uint32_t u0 = *reinterpret_cast<uint32_t*>(&p0);
    uint32_t u1 = *reinterpret_cast<uint32_t*>(&p1);
    unsigned long long r;
    asm("mov.b64 %0, {%1, %2};" : "=l"(r) : "r"(u0), "r"(u1));
    return r;
}
#define FMA2(d, a, b) \
    asm("fma.rn.f32x2 %0, %1, %2, %0;" : "+l"(d) : "l"(a), "l"(b))
__device__ __forceinline__ unsigned long long pack_dup(float x) {
    unsigned long long r;
    unsigned int u = __float_as_uint(x);
    asm("mov.b64 %0, {%1, %2};" : "=l"(r) : "r"(u), "r"(u));
    return r;
}
__device__ __forceinline__ float2 bf2_to_f2(uint32_t u) {
    __nv_bfloat162 b = *reinterpret_cast<__nv_bfloat162*>(&u);
    return __bfloat1622float2(b);
}

#if USE_TCGEN05
// ---------------- PTX helpers (sm_103a-only pass) ----------------
__device__ __forceinline__ uint32_t elect_one_pred() {
    uint32_t pred;
    asm volatile("{\n\t.reg .pred p;\n\telect.sync _|p, 0xFFFFFFFF;\n\tselp.b32 %0, 1, 0, p;\n\t}" : "=r"(pred));
    return pred;
}
#define MBARRIER_INIT(a, c) \
    asm volatile("mbarrier.init.shared.b64 [%0], %1;" :: "r"((uint32_t)(a)), "r"((uint32_t)(c)) : "memory")
#define MBARRIER_INVAL(a) \
    asm volatile("mbarrier.inval.shared.b64 [%0];" :: "r"((uint32_t)(a)) : "memory")
#define MBARRIER_ARRIVE(a) \
    asm volatile("mbarrier.arrive.shared.b64 _, [%0];" :: "r"((uint32_t)(a)) : "memory")
#define MBARRIER_WAIT_PARITY(mbar_smem_addr, phase_parity) do { \
    uint32_t _mbar = (uint32_t)(mbar_smem_addr); \
    uint32_t _parity = (uint32_t)(phase_parity); \
    uint32_t _done; \
    asm volatile("{\n\t.reg .pred p;\n\t" \
        "mbarrier.try_wait.parity.acquire.cta.shared::cta.b64 p, [%1], %2;\n\t" \
        "selp.b32 %0, 1, 0, p;\n\t}" \
        : "=r"(_done) : "r"(_mbar), "r"(_parity) : "memory"); \
    if (!_done) { \
        asm volatile("{\n\t.reg .pred P1;\n\t" \
            "WAIT_LOOP_%=:\n\t" \
            "mbarrier.try_wait.parity.acquire.cta.shared::cta.b64 P1, [%0], %1, 0x989680;\n\t" \
            "@P1 bra.uni WAIT_DONE_%=;\n\t" \
            "bra.uni WAIT_LOOP_%=;\n\t" \
            "WAIT_DONE_%=:\n\t}" \
            :: "r"(_mbar), "r"(_parity) : "memory"); \
    } \
} while(0)
#define TCGEN05_ALLOC(sa, n) \
    asm volatile("tcgen05.alloc.cta_group::1.sync.aligned.shared::cta.b32 [%0], %1;" \
                 :: "r"((uint32_t)(sa)), "r"((uint32_t)(n)) : "memory")
#define TCGEN05_DEALLOC(t, n) \
    asm volatile("tcgen05.dealloc.cta_group::1.sync.aligned.b32 %0, %1;" :: "r"(t), "r"((uint32_t)(n)))
#define TCGEN05_RELINQUISH() \
    asm volatile("tcgen05.relinquish_alloc_permit.cta_group::1.sync.aligned;")
#define TCGEN05_COMMIT(a) \
    asm volatile("tcgen05.commit.cta_group::1.mbarrier::arrive::one.shared::cluster.b64 [%0];" \
                 :: "r"((uint32_t)(a)) : "memory")
#define TCGEN05_FENCE_AFTER()  asm volatile("tcgen05.fence::after_thread_sync;" ::: "memory")
#define TCGEN05_FENCE_BEFORE() asm volatile("tcgen05.fence::before_thread_sync;" ::: "memory")
#define TCGEN05_WAIT_LD()      asm volatile("tcgen05.wait::ld.sync.aligned;" ::: "memory")
#define FENCE_PROXY_ASYNC()    asm volatile("fence.proxy.async.shared::cta;" ::: "memory")
#define CP_ASYNC_16(dst, src) \
    asm volatile("cp.async.cg.shared.global [%0], [%1], 16;" :: "r"((uint32_t)(dst)), "l"(src) : "memory")
// completion-gated arrival: fires one arrival on [bar] when all prior cp.async
// of this thread have completed. .noinc => expected count fixed at init.
#define CP_ASYNC_MBAR_ARRIVE(bar) \
    asm volatile("cp.async.mbarrier.arrive.noinc.shared.b64 [%0];" :: "r"((uint32_t)(bar)) : "memory")

#define TCGEN05_LD_32X32B_X32(r, ta) \
    asm volatile( \
        "tcgen05.ld.sync.aligned.32x32b.x32.b32 " \
        "{%0, %1, %2, %3, %4, %5, %6, %7, " \
        " %8, %9, %10, %11, %12, %13, %14, %15, " \
        " %16, %17, %18, %19, %20, %21, %22, %23, " \
        " %24, %25, %26, %27, %28, %29, %30, %31}, [%32];" \
        : "=r"((r)[0]),  "=r"((r)[1]),  "=r"((r)[2]),  "=r"((r)[3]), \
          "=r"((r)[4]),  "=r"((r)[5]),  "=r"((r)[6]),  "=r"((r)[7]), \
          "=r"((r)[8]),  "=r"((r)[9]),  "=r"((r)[10]), "=r"((r)[11]), \
          "=r"((r)[12]), "=r"((r)[13]), "=r"((r)[14]), "=r"((r)[15]), \
          "=r"((r)[16]), "=r"((r)[17]), "=r"((r)[18]), "=r"((r)[19]), \
          "=r"((r)[20]), "=r"((r)[21]), "=r"((r)[22]), "=r"((r)[23]), \
          "=r"((r)[24]), "=r"((r)[25]), "=r"((r)[26]), "=r"((r)[27]), \
          "=r"((r)[28]), "=r"((r)[29]), "=r"((r)[30]), "=r"((r)[31]) \
        : "r"(ta))

static constexpr uint64_t DESC_BASE_SW128 =
    (uint64_t(2) << 61) | (uint64_t(1) << 46) | (uint64_t(64) << 32) | (uint64_t(1) << 16);
#define MAKE_DESC(sa) (DESC_BASE_SW128 | ((uint64_t)((sa) >> 4) & 0x3FFF))
#define SMEM_SWIZZLE_128B(b)   ((b) ^ (((b) >> 3) & 0x70))

// idesc kind::f16, bf16 x bf16 -> f32, M=128, N=256 (use full TMEM width)
static constexpr uint32_t GEMM_IDESC =
    (1u << 4) | (1u << 7) | (1u << 10) | ((256u / 8) << 17) | ((128u / 16) << 24);

__device__ __forceinline__ void mma_f16_ss(uint32_t d, uint64_t a, uint64_t b,
                                           uint32_t idesc, uint32_t en) {
    asm volatile(
        "{\n\t.reg .pred p;\n\tsetp.ne.u32 p, %4, 0;\n\t"
        "tcgen05.mma.cta_group::1.kind::f16 [%0], %1, %2, %3, {%5, %5, %5, %5}, p;\n\t}"
        :: "r"(d), "l"(a), "l"(b), "r"(idesc), "r"(en), "r"(0u) : "memory");
}
#endif // USE_TCGEN05

// ---------------- pre-pass: transpose + split (Q, K only) ----------------
// src [n][R][L] fp32 (L contiguous) -> dh/dl [n][L][R] bf16 (bf162 stores)
__global__ __launch_bounds__(256) void transpose_split_kernel(
    const float* __restrict__ src, __nv_bfloat16* __restrict__ dh,
    __nv_bfloat16* __restrict__ dl, int R, int L) {
    __shared__ float tile[32][33];
    const int n = blockIdx.z;
    const float* s = src + (size_t)n * R * L;
    __nv_bfloat16* ph = dh + (size_t)n * R * L;
    __nv_bfloat16* pl = dl + (size_t)n * R * L;
    const int tx = threadIdx.x, ty = threadIdx.y;
    const int x  = blockIdx.x * 32 + tx;    // L index
    const int y0 = blockIdx.y * 32;         // R base
    #pragma unroll
    for (int j = 0; j < 4; j++)
        tile[ty + j * 8][tx] = s[(size_t)(y0 + ty + j * 8) * L + x];
    __syncthreads();
    const int yb  = blockIdx.x * 32;        // L base
    const int tid = ty * 32 + tx;
    #pragma unroll
    for (int it = 0; it < 2; it++) {
        const int wi = tid + it * 256;      // 0..511
        const int yo = wi >> 4;             // L col 0..31
        const int p  = wi & 15;             // R pair 0..15
        float v0 = tile[2 * p + 0][yo];
        float v1 = tile[2 * p + 1][yo];
        __nv_bfloat16 h0, l0, h1, l1;
        split2(v0, h0, l0); split2(v1, h1, l1);
        const size_t o = ((size_t)(yb + yo) * R + y0 + 2 * p) >> 1;
        ((__nv_bfloat162*)ph)[o] = __nv_bfloat162(h0, h1);
        ((__nv_bfloat162*)pl)[o] = __nv_bfloat162(l0, l1);
    }
}

// ---------------- softmax: logits fp32 -> W bf16 hi/lo ----------------
__global__ __launch_bounds__(256) void softmax_kernel(const float* __restrict__ ratios) {
    const int warp = threadIdx.x >> 5;
    const int lane = threadIdx.x & 31;
    const int row  = blockIdx.x * 8 + warp;   // n*CC + c
    const int n    = row >> 9;
    const float r = ratios[n];
    const int vw  = min(WDIM, (int)floorf((float)WDIM * r + 0.5f));

    const float* p = g_logits + (size_t)row * TT;
    float v[32];
    float mx = -INFINITY;
    #pragma unroll
    for (int i = 0; i < 32; i++) {
        const int t = lane + i * 32;
        float x = p[t] * SCALE_F;
        if ((t & (WDIM - 1)) >= vw) x = -INFINITY;
        v[i] = x; mx = fmaxf(mx, x);
    }
    #pragma unroll
    for (int off = 16; off > 0; off >>= 1)
        mx = fmaxf(mx, __shfl_xor_sync(0xffffffffu, mx, off));
    float s = 0.0f;
    #pragma unroll
    for (int i = 0; i < 32; i++) { const float e = expf(v[i] - mx); v[i] = e; s += e; }
    #pragma unroll
    for (int off = 16; off > 0; off >>= 1)
        s += __shfl_xor_sync(0xffffffffu, s, off);
    const float inv = 1.0f / s;
    __nv_bfloat16* wh = g_Wh + (size_t)row * TT;
    __nv_bfloat16* wl = g_Wl + (size_t)row * TT;
    #pragma unroll
    for (int i = 0; i < 32; i++) {
        __nv_bfloat16 h, l; split2(v[i] * inv, h, l);
        wh[lane + i * 32] = h; wl[lane + i * 32] = l;
    }
}

// ---------------- GEMM: D[m][nn] = sum_k A[m][k]*B[nn][k] ----------------
// Warp-specialized tcgen05, 384 threads, tile 128(M) x 256(N), BK=64, 2-stage
// ring. Warp 0 = MMA issuer; warps 4-7 = A producer (CONV_A: fp32->hi/lo split
// in-flight; else cp.async); warps 8-11 = B producer (cp.async). D uses 256
// TMEM cols (the previously idle half) -> 25% fewer fill bytes per MAC and a
// 1536-cyc MMA window per chunk (vs 768) that hides fill latency.
#define SM_TMEM  0
#define SM_FULL  8     // 2 x 8B
#define SM_EMPTY 24    // 2 x 8B
#define SM_DONE  40    // 8B, single-use
#define SM_DATA  1024
#define A_TILE_B 16384          // 128 rows x 128B (hi or lo)
#define B_TILE_B 32768          // 256 rows x 128B (hi or lo)
#define CHUNK_B  (2 * A_TILE_B + 2 * B_TILE_B)   // 98304
#define OFF_AH   0
#define OFF_AL   A_TILE_B
#define OFF_BH   (2 * A_TILE_B)
#define OFF_BL   (2 * A_TILE_B + B_TILE_B)
#define STAGES   2
#define GEMM_SMEM (1024 + STAGES * CHUNK_B)      // 197632 B

template <bool CONV_A>
__global__ __launch_bounds__(384, 1)
void gemm_split_kernel(const float* __restrict__ Afp,
                       const __nv_bfloat16* __restrict__ Ah, const __nv_bfloat16* __restrict__ Al,
                       const __nv_bfloat16* __restrict__ Bh, const __nv_bfloat16* __restrict__ Bl,
                       float* __restrict__ C, int Kdim, int ldc,
                       size_t sA, size_t sB, size_t sC) {
    extern __shared__ char smem[];
    const int tid = threadIdx.x, wid = tid >> 5, lane = tid & 31;
    const int nz = blockIdx.z, m0 = blockIdx.y * 128, n0 = blockIdx.x * 256;

#if USE_TCGEN05
    const uint32_t sb = smem_to_u32(smem);

    if (wid == 0) { TCGEN05_ALLOC(sb + SM_TMEM, 256); TCGEN05_RELINQUISH(); }
    if (tid == 0) {
        #pragma unroll
        for (int s = 0; s < STAGES; s++) {
            MBARRIER_INIT(sb + SM_FULL  + 8 * s, 256);  // 128 A + 128 B arrivals
            MBARRIER_INIT(sb + SM_EMPTY + 8 * s, 1);    // tcgen05 commit
        }
        MBARRIER_INIT(sb + SM_DONE, 1);                 // final completion
    }
    __syncthreads();
    uint32_t tmem;
    asm volatile("ld.shared.b32 %0, [%1];" : "=r"(tmem) : "r"(sb + SM_TMEM));

    const int nch = Kdim >> 6;

    if (wid >= 4 && wid < 8) {
        // ---- A producer (128 threads): 32KB/chunk ----
        const int f = tid - 128;              // 0..127
        for (int ch = 0; ch < nch; ch++) {
            const int s = ch % STAGES;
            if (ch >= STAGES)
                MBARRIER_WAIT_PARITY(sb + SM_EMPTY + 8 * s, ((ch - STAGES) / STAGES) & 1);
            const int k0 = ch << 6;
            const uint32_t stg = (uint32_t)SM_DATA + (uint32_t)s * CHUNK_B;
            if (CONV_A) {
                // read fp32 A (32KB), split to bf16 hi/lo, store swizzled
                const float* gs = Afp + nz * sA + (size_t)m0 * Kdim + k0;
                char* tbh = smem + stg + OFF_AH;
                char* tbl = smem + stg + OFF_AL;
                #pragma unroll
                for (int i = 0; i < 16; i++) {
                    const int idx = f + 128 * i;
                    const int r = idx >> 4, c4 = idx & 15;
                    float4 u = *(const float4*)(gs + (size_t)r * Kdim + c4 * 4);
                    __nv_bfloat16 h0, l0, h1, l1, h2, l2, h3, l3;
                    split2(u.x, h0, l0); split2(u.y, h1, l1);
                    split2(u.z, h2, l2); split2(u.w, h3, l3);
                    const uint32_t off = SMEM_SWIZZLE_128B((uint32_t)(r * 128 + c4 * 8));
                    *(unsigned long long*)(tbh + off) = pack4(h0, h1, h2, h3);
                    *(unsigned long long*)(tbl + off) = pack4(l0, l1, l2, l3);
                }
                MBARRIER_ARRIVE(sb + SM_FULL + 8 * s);   // release-arrive after STS
            } else {
                #pragma unroll
                for (int tg = 0; tg < 2; tg++) {
                    const uint32_t tb = sb + stg + (tg ? OFF_AL : OFF_AH);
                    const __nv_bfloat16* gs =
                        (tg ? Al : Ah) + nz * sA + (size_t)m0 * Kdim + k0;
                    #pragma unroll
                    for (int i = 0; i < 8; i++) {
                        const int idx = f + 128 * i;
                        const int r = idx >> 3, c = idx & 7;
                        const uint32_t dst = tb + SMEM_SWIZZLE_128B((uint32_t)(r * 128 + c * 16));
                        CP_ASYNC_16(dst, (const void*)(gs + (size_t)r * Kdim + c * 8));
                    }
                }
                CP_ASYNC_MBAR_ARRIVE(sb + SM_FULL + 8 * s);
            }
        }
    } else if (wid >= 8) {
        // ---- B producer (128 threads, cp.async): 64KB/chunk (256 rows) ----
        const int f = tid - 256;
        for (int ch = 0; ch < nch; ch++) {
            const int s = ch % STAGES;
            if (ch >= STAGES)
                MBARRIER_WAIT_PARITY(sb + SM_EMPTY + 8 * s, ((ch - STAGES) / STAGES) & 1);
            const int k0 = ch << 6;
            const uint32_t stg = (uint32_t)SM_DATA + (uint32_t)s * CHUNK_B;
            #pragma unroll
            for (int tg = 0; tg < 2; tg++) {
                const uint32_t tb = sb + stg + (tg ? OFF_BL : OFF_BH);
                const __nv_bfloat16* gs =
                    (tg ? Bl : Bh) + nz * sB + (size_t)n0 * Kdim + k0;
                #pragma unroll
                for (int i = 0; i < 16; i++) {
                    const int idx = f + 128 * i;
                    const int r = idx >> 3, c = idx & 7;   // r: 0..255
                    const uint32_t dst = tb + SMEM_SWIZZLE_128B((uint32_t)(r * 128 + c * 16));
                    CP_ASYNC_16(dst, (const void*)(gs + (size_t)r * Kdim + c * 8));
                }
            }
            CP_ASYNC_MBAR_ARRIVE(sb + SM_FULL + 8 * s);
        }
    } else if (wid == 0) {
        // ---- consumer: MMA issue, paced by tensor queue ----
        for (int ch = 0; ch < nch; ch++) {
            const int s = ch % STAGES;
            MBARRIER_WAIT_PARITY(sb + SM_FULL + 8 * s, (ch / STAGES) & 1);
            FENCE_PROXY_ASYNC();
            if (elect_one_pred()) {
                const uint32_t stg = (uint32_t)SM_DATA + (uint32_t)s * CHUNK_B;
                const uint64_t dAh = MAKE_DESC(sb + stg + OFF_AH);
                const uint64_t dAl = MAKE_DESC(sb + stg + OFF_AL);
                const uint64_t dBh = MAKE_DESC(sb + stg + OFF_BH);
                const uint64_t dBl = MAKE_DESC(sb + stg + OFF_BL);
                #pragma unroll
                for (int p = 0; p < 3; p++) {
                    const uint64_t da = (p == 2) ? dAl : dAh;
                    const uint64_t db = (p == 1) ? dBl : dBh;
                    #pragma unroll
                    for (int ks = 0; ks < 4; ks++) {
                        const uint32_t en = !(ch == 0 && p == 0 && ks == 0);
                        mma_f16_ss(tmem, da + ks * 2, db + ks * 2, GEMM_IDESC, en);
                    }
                }
                TCGEN05_COMMIT(sb + SM_EMPTY + 8 * s);
            }
        }
        // single-use completion signal: fires when ALL prior MMAs complete
        if (elect_one_pred()) TCGEN05_COMMIT(sb + SM_DONE);
    }
    // ---- all warps: unambiguous final wait (done used exactly once) ----
    MBARRIER_WAIT_PARITY(sb + SM_DONE, 0);
    TCGEN05_FENCE_AFTER();

    if (wid < 4) {
        float* Crow = C + nz * sC + (size_t)(m0 + wid * 32 + lane) * ldc + n0;
        #pragma unroll
        for (int nb = 0; nb < 8; nb++) {
            uint32_t r[32];
            TCGEN05_LD_32X32B_X32(r, tmem + nb * 32);
            TCGEN05_WAIT_LD();
            #pragma unroll
            for (int j = 0; j < 8; j++) {
                float4 v;
                v.x = __uint_as_float(r[j * 4 + 0]);
                v.y = __uint_as_float(r[j * 4 + 1]);
                v.z = __uint_as_float(r[j * 4 + 2]);
                v.w = __uint_as_float(r[j * 4 + 3]);
                *(float4*)(Crow + nb * 32 + j * 4) = v;
            }
        }
        TCGEN05_FENCE_BEFORE();
    }
    __syncthreads();
    if (tid == 0) {
        #pragma unroll
        for (int s = 0; s < STAGES; s++) {
            MBARRIER_INVAL(sb + SM_FULL + 8 * s);
            MBARRIER_INVAL(sb + SM_EMPTY + 8 * s);
        }
        MBARRIER_INVAL(sb + SM_DONE);
    }
    __syncthreads();
    if (wid == 0) TCGEN05_DEALLOC(tmem, 256);

#else
    // ---- SIMT fallback: fp32, 128(M) x 256(N) tile via two 128-wide halves ----
    float* As = (float*)smem;                       // [16][136]
    float* Bs = (float*)(smem + 16 * 136 * 4);      // [16][136]
    const int tx = tid & 15;
    const int ty = (tid & 255) >> 4;
    const int lr = (tid & 255) >> 1;
    const int lk = (tid & 1) * 8;
    const bool active = tid < 256;

    for (int nh = 0; nh < 2; nh++) {
        const int n0h = n0 + nh * 128;
        unsigned long long acc[8][4];
        #pragma unroll
        for (int i = 0; i < 8; i++)
            #pragma unroll
            for (int j = 0; j < 4; j++) acc[i][j] = 0ull;

        for (int k0 = 0; k0 < Kdim; k0 += 16) {
            if (active) {
                if (CONV_A) {
                    const float* pA = Afp + nz * sA + (size_t)m0 * Kdim;
                    const float4 u0 = *(const float4*)(pA + (size_t)lr * Kdim + k0 + lk);
                    const float4 u1 = *(const float4*)(pA + (size_t)lr * Kdim + k0 + lk + 4);
                    const float fv[8] = {u0.x, u0.y, u0.z, u0.w, u1.x, u1.y, u1.z, u1.w};
                    #pragma unroll
                    for (int j = 0; j < 8; j++)
                        As[(lk + j) * 136 + lr] = fv[j];
                } else {
                    const __nv_bfloat16* pAh = Ah + nz * sA + (size_t)m0 * Kdim;
                    const __nv_bfloat16* pAl = Al + nz * sA + (size_t)m0 * Kdim;
                    uint4 uh = *(const uint4*)(pAh + (size_t)lr * Kdim + k0 + lk);
                    uint4 ul = *(const uint4*)(pAl + (size_t)lr * Kdim + k0 + lk);
                    const uint32_t hh[4] = {uh.x, uh.y, uh.z, uh.w};
                    const uint32_t ll[4] = {ul.x, ul.y, ul.z, ul.w};
                    #pragma unroll
                    for (int j = 0; j < 4; j++) {
                        float2 h = bf2_to_f2(hh[j]), l = bf2_to_f2(ll[j]);
                        As[(lk + j * 2 + 0) * 136 + lr] = h.x + l.x;
                        As[(lk + j * 2 + 1) * 136 + lr] = h.y + l.y;
                    }
                }
                {
                    const __nv_bfloat16* pBh = Bh + nz * sB + (size_t)n0h * Kdim;
                    const __nv_bfloat16* pBl = Bl + nz * sB + (size_t)n0h * Kdim;
                    uint4 uh = *(const uint4*)(pBh + (size_t)lr * Kdim + k0 + lk);
                    uint4 ul = *(const uint4*)(pBl + (size_t)lr * Kdim + k0 + lk);
                    const uint32_t hh[4] = {uh.x, uh.y, uh.z, uh.w};
                    const uint32_t ll[4] = {ul.x, ul.y, ul.z, ul.w};
                    #pragma unroll
                    for (int j = 0; j < 4; j++) {
                        float2 h = bf2_to_f2(hh[j]), l = bf2_to_f2(ll[j]);
                        Bs[(lk + j * 2 + 0) * 136 + lr] = h.x + l.x;
                        Bs[(lk + j * 2 + 1) * 136 + lr] = h.y + l.y;
                    }
                }
            }
            __syncthreads();
            if (active) {
                #pragma unroll
                for (int kk = 0; kk < 16; kk++) {
                    float4 a0 = *(const float4*)&As[kk * 136 + ty * 8 + 0];
                    float4 a1 = *(const float4*)&As[kk * 136 + ty * 8 + 4];
                    unsigned long long b0 = *(const unsigned long long*)&Bs[kk * 136 + tx * 8 + 0];
                    unsigned long long b1 = *(const unsigned long long*)&Bs[kk * 136 + tx * 8 + 2];
                    unsigned long long b2 = *(const unsigned long long*)&Bs[kk * 136 + tx * 8 + 4];
                    unsigned long long b3 = *(const unsigned long long*)&Bs[kk * 136 + tx * 8 + 6];
                    float am[8] = {a0.x, a0.y, a0.z, a0.w, a1.x, a1.y, a1.z, a1.w};
                    #pragma unroll
                    for (int m = 0; m < 8; m++) {
                        unsigned long long A2 = pack_dup(am[m]);
                        FMA2(acc[m][0], A2, b0);
                        FMA2(acc[m][1], A2, b1);
                        FMA2(acc[m][2], A2, b2);
                        FMA2(acc[m][3], A2, b3);
                    }
                }
            }
            __syncthreads();
        }

        if (active) {
            #pragma unroll
            for (int m = 0; m < 8; m++) {
                float* Crow = C + nz * sC + (size_t)(m0 + ty * 8 + m) * ldc + n0h + tx * 8;
                #pragma unroll
                for (int p = 0; p < 4; p++)
                    *(unsigned long long*)(Crow + p * 2) = acc[m][p];
            }
        }
        __syncthreads();
    }
#endif
}

// ---------------- launch ----------------
extern "C" void kernel_launch(void* const* d_in, const int* in_sizes, int n_in,
                              void* d_out, int out_size) {
    const float* q      = (const float*)d_in[0];
    const float* k      = (const float*)d_in[1];
    const float* v      = (const float*)d_in[2];
    const float* ratios = (const float*)d_in[3];
    float* out = (float*)d_out;
    (void)in_sizes; (void)n_in; (void)out_size;

    float* lg; __nv_bfloat16 *qh, *ql, *kh, *kl, *wh, *wl;
    cudaGetSymbolAddress((void**)&lg, g_logits);
    cudaGetSymbolAddress((void**)&qh, g_Qth); cudaGetSymbolAddress((void**)&ql, g_Qtl);
    cudaGetSymbolAddress((void**)&kh, g_Kth); cudaGetSymbolAddress((void**)&kl, g_Ktl);
    cudaGetSymbolAddress((void**)&wh, g_Wh);  cudaGetSymbolAddress((void**)&wl, g_Wl);

    cudaFuncSetAttribute(gemm_split_kernel<false>,
                         cudaFuncAttributeMaxDynamicSharedMemorySize, GEMM_SMEM);
    cudaFuncSetAttribute(gemm_split_kernel<true>,
                         cudaFuncAttributeMaxDynamicSharedMemorySize, GEMM_SMEM);

    // pre-pass: Qt[c][d], Kt[t][d] (V split is fused into GEMM2's producer)
    transpose_split_kernel<<<dim3(CC / 32, DD / 32, NB), dim3(32, 8)>>>(q, qh, ql, DD, CC);
    transpose_split_kernel<<<dim3(TT / 32, DD / 32, NB), dim3(32, 8)>>>(k, kh, kl, DD, TT);

    // GEMM1: logits[c][t] = Qt[c][:] . Kt[t][:]   (K=512), A via cp.async
    gemm_split_kernel<false><<<dim3(TT / 256, CC / 128, NB), 384, GEMM_SMEM>>>(
        nullptr, qh, ql, kh, kl, lg, DD, TT,
        (size_t)CC * DD, (size_t)TT * DD, (size_t)CC * TT);

    softmax_kernel<<<(NB * CC) / 8, 256>>>(ratios);

    // GEMM2: out[dd][c] = V[dd][:] . W[c][:]      (K=1024), A = fp32 V split in-flight
    gemm_split_kernel<true><<<dim3(CC / 256, DD / 128, NB), 384, GEMM_SMEM>>>(
        v, nullptr, nullptr, wh, wl, out, TT, CC,
        (size_t)DD * TT, (size_t)CC * TT, (size_t)DD * CC);
}